// round 1
// baseline (speedup 1.0000x reference)
#include <cuda_runtime.h>

// LinearInverse_45664092291621
//
// Reference analysis:
//   score(x) = -x, and the function returns  y + score(y) = y - y = 0
//   for every finite y. The 199-step Langevin-style scan, the JAX Threefry
//   noise, the convergence flag — all of it is dead code w.r.t. the output.
//   The reference output is exactly zeros((1048576, 2), float32).
//
// So the optimal kernel is a single coalesced zero-fill of d_out
// (out_size floats = 8 MB). Write-only DRAM bound; ~1.5-2.5 us of pure
// store traffic plus launch overhead.

__global__ void __launch_bounds__(256) zero_fill_v4(float4* __restrict__ out, int n4) {
    int i = blockIdx.x * blockDim.x + threadIdx.x;
    if (i < n4) {
        out[i] = make_float4(0.0f, 0.0f, 0.0f, 0.0f);
    }
}

__global__ void __launch_bounds__(256) zero_fill_tail(float* __restrict__ out, int start, int n) {
    int i = start + blockIdx.x * blockDim.x + threadIdx.x;
    if (i < n) {
        out[i] = 0.0f;
    }
}

extern "C" void kernel_launch(void* const* d_in, const int* in_sizes, int n_in,
                              void* d_out, int out_size) {
    (void)d_in; (void)in_sizes; (void)n_in;

    float* out = (float*)d_out;

    int n4 = out_size >> 2;           // number of full float4s
    int vec_elems = n4 << 2;          // elements covered by vector stores

    if (n4 > 0) {
        int threads = 256;
        int blocks = (n4 + threads - 1) / threads;
        zero_fill_v4<<<blocks, threads>>>((float4*)out, n4);
    }
    if (vec_elems < out_size) {
        int rem = out_size - vec_elems;
        zero_fill_tail<<<1, 32>>>(out, vec_elems, out_size);
        (void)rem;
    }
}